// round 3
// baseline (speedup 1.0000x reference)
#include <cuda_runtime.h>
#include <cuda_fp16.h>
#include <cuda_fp8.h>
#include <cstdint>

#define M_DIM 16384
#define N_DIM 4096
#define K_DIM 4096

#define BM 128
#define BN 128
#define BK 64
#define STAGES 3
#define KITERS (K_DIM / BK)            // 64
#define A_BYTES (BM * BK * 2)          // 16384
#define B_BYTES (BK * BN * 2)          // 16384
#define STAGE_BYTES (A_BYTES + B_BYTES)
#define GEMM_SMEM (STAGES * STAGE_BYTES)  // 98304

// Scratch (device globals: allocation-free rule). 128MB + 32MB.
__device__ __align__(1024) __half g_A[(size_t)M_DIM * K_DIM];  // [M,K] dequant fp16
__device__ __align__(1024) __half g_B[(size_t)K_DIM * N_DIM];  // [K,N] dequant fp16

__device__ __forceinline__ uint32_t smem_u32(const void* p) {
    uint32_t a;
    asm("{ .reg .u64 t; cvta.to.shared.u64 t, %1; cvt.u32.u64 %0, t; }" : "=r"(a) : "l"(p));
    return a;
}

// ============================ quantization =================================
// Exactly reproduce: scale = max(amax/448, 1e-12); q = e4m3_rne(x/scale); deq = q*scale
__device__ __forceinline__ void quant4(const float4 v, __half* h) {
    float amax = fmaxf(fmaxf(fabsf(v.x), fabsf(v.y)), fmaxf(fabsf(v.z), fabsf(v.w)));
    #pragma unroll
    for (int o = 16; o; o >>= 1) amax = fmaxf(amax, __shfl_xor_sync(0xFFFFFFFFu, amax, o));
    float scale = fmaxf(__fdiv_rn(amax, 448.0f), 1e-12f);
    float f[4] = {v.x, v.y, v.z, v.w};
    #pragma unroll
    for (int j = 0; j < 4; j++) {
        __nv_fp8_storage_t q =
            __nv_cvt_float_to_fp8(__fdiv_rn(f[j], scale), __NV_SATFINITE, __NV_E4M3);
        __half_raw hr = __nv_cvt_fp8_to_halfraw(q, __NV_E4M3);
        float dq = __half2float(*reinterpret_cast<__half*>(&hr)) * scale;
        h[j] = __float2half_rn(dq);
    }
}

// x [M,K], 128-blocks along K. One warp per block. -> g_A same layout.
__global__ void __launch_bounds__(256) quant_x_kernel(const float* __restrict__ x) {
    int w = blockIdx.x * 8 + (threadIdx.x >> 5);
    int lane = threadIdx.x & 31;
    int m = w >> 5, kb = w & 31;
    size_t off = (size_t)m * K_DIM + kb * 128 + lane * 4;
    float4 v = *(const float4*)(x + off);
    __half h[4];
    quant4(v, h);
    *(uint2*)(g_A + off) = *(uint2*)h;
}

// kernel [K,N], 128-blocks along N. One warp per block. -> g_B same layout.
__global__ void __launch_bounds__(256) quant_w_kernel(const float* __restrict__ kn) {
    int w = blockIdx.x * 8 + (threadIdx.x >> 5);
    int lane = threadIdx.x & 31;
    int k = w >> 5, nb = w & 31;
    size_t off = (size_t)k * N_DIM + nb * 128 + lane * 4;
    float4 v = *(const float4*)(kn + off);
    __half h[4];
    quant4(v, h);
    *(uint2*)(g_B + off) = *(uint2*)h;
}

// ============================ GEMM =========================================
// A smem: [128 m][64 k] halves, 128B rows, SW128 swizzle.
// B smem: [64 k][128 n] halves, two 64-n panels of 128B rows, SW128 swizzle.
__device__ __forceinline__ void load_stage(uint32_t stage_base, size_t m0, size_t n0,
                                           int tid, int chunk) {
    const int k0 = chunk * BK;
    uint32_t sA = stage_base;
    uint32_t sB = stage_base + A_BYTES;
    #pragma unroll
    for (int j = 0; j < 4; j++) {
        int i = tid + j * 256;
        int r = i >> 3, c = i & 7;
        uint64_t ga = __cvta_generic_to_global(g_A + (m0 + r) * (size_t)K_DIM + k0 + c * 8);
        uint32_t sa = sA + r * 128 + ((c * 16) ^ ((r & 7) * 16));
        asm volatile("cp.async.cg.shared.global [%0], [%1], 16;" :: "r"(sa), "l"(ga));
    }
    #pragma unroll
    for (int j = 0; j < 4; j++) {
        int i = tid + j * 256;
        int r = i >> 4, c = i & 15;
        uint64_t gb = __cvta_generic_to_global(g_B + (size_t)(k0 + r) * N_DIM + n0 + c * 8);
        uint32_t sbp = sB + (c >> 3) * 8192 + r * 128 + (((c & 7) * 16) ^ ((r & 7) * 16));
        asm volatile("cp.async.cg.shared.global [%0], [%1], 16;" :: "r"(sbp), "l"(gb));
    }
    asm volatile("cp.async.commit_group;" ::: "memory");
}

__global__ void __launch_bounds__(256, 2) gemm_kernel(const float* __restrict__ bias,
                                                      float* __restrict__ out) {
    extern __shared__ char smem_raw[];
    uint32_t sb = smem_u32(smem_raw);
    int tid = threadIdx.x, wid = tid >> 5, lane = tid & 31;

    // tile mapping with M-group swizzle for L2 reuse (8 mt x 32 nt per group)
    int bid = blockIdx.x;
    int g = bid >> 8, r = bid & 255;
    int mt = g * 8 + (r & 7);
    int nt = r >> 3;
    size_t m0 = (size_t)mt * BM, n0 = (size_t)nt * BN;
    int wm = (wid & 3) * 32, wn = (wid >> 2) * 64;

    float d[2][8][4];
    #pragma unroll
    for (int i = 0; i < 2; i++)
        #pragma unroll
        for (int j = 0; j < 8; j++)
            #pragma unroll
            for (int q = 0; q < 4; q++) d[i][j][q] = 0.0f;

    load_stage(sb, m0, n0, tid, 0);
    load_stage(sb + STAGE_BYTES, m0, n0, tid, 1);

    for (int it = 0; it < KITERS; it++) {
        int s = it % 3;
        if (it + 2 < KITERS) asm volatile("cp.async.wait_group 1;" ::: "memory");
        else                 asm volatile("cp.async.wait_group 0;" ::: "memory");
        __syncthreads();
        if (it + 2 < KITERS)
            load_stage(sb + ((it + 2) % 3) * STAGE_BYTES, m0, n0, tid, it + 2);

        uint32_t sA = sb + s * STAGE_BYTES;
        uint32_t sB = sA + A_BYTES;

        #pragma unroll
        for (int ks = 0; ks < 4; ks++) {
            uint32_t a[2][4], b[8][2];
            // A fragments: two 16x16 tiles
            #pragma unroll
            for (int am = 0; am < 2; am++) {
                int row = wm + am * 16 + (lane & 15);
                int cb = ks * 32 + (lane >> 4) * 16;
                uint32_t addr = sA + row * 128 + (cb ^ ((row & 7) * 16));
                asm volatile(
                    "ldmatrix.sync.aligned.m8n8.x4.shared.b16 {%0,%1,%2,%3}, [%4];"
                    : "=r"(a[am][0]), "=r"(a[am][1]), "=r"(a[am][2]), "=r"(a[am][3])
                    : "r"(addr));
            }
            // B fragments: eight 16x8 (k x n) tiles via four x4.trans loads
            #pragma unroll
            for (int q = 0; q < 4; q++) {
                int krow = ks * 16 + (lane & 7) + ((lane & 8) ? 8 : 0);
                int ncol = wn + q * 16 + (lane >> 4) * 8;
                uint32_t addr = sB + (ncol >> 6) * 8192 + krow * 128 +
                                (((ncol & 63) * 2) ^ ((krow & 7) * 16));
                uint32_t r0, r1, r2, r3;
                asm volatile(
                    "ldmatrix.sync.aligned.m8n8.x4.trans.shared.b16 {%0,%1,%2,%3}, [%4];"
                    : "=r"(r0), "=r"(r1), "=r"(r2), "=r"(r3)
                    : "r"(addr));
                b[q * 2][0] = r0; b[q * 2][1] = r1;
                b[q * 2 + 1][0] = r2; b[q * 2 + 1][1] = r3;
            }
            #pragma unroll
            for (int am = 0; am < 2; am++)
                #pragma unroll
                for (int bn = 0; bn < 8; bn++) {
                    asm volatile(
                        "mma.sync.aligned.m16n8k16.row.col.f32.f16.f16.f32 "
                        "{%0,%1,%2,%3}, {%4,%5,%6,%7}, {%8,%9}, {%0,%1,%2,%3};"
                        : "+f"(d[am][bn][0]), "+f"(d[am][bn][1]),
                          "+f"(d[am][bn][2]), "+f"(d[am][bn][3])
                        : "r"(a[am][0]), "r"(a[am][1]), "r"(a[am][2]), "r"(a[am][3]),
                          "r"(b[bn][0]), "r"(b[bn][1]));
                }
        }
    }

    // Epilogue: direct register -> gmem, add bias.
    #pragma unroll
    for (int am = 0; am < 2; am++) {
        size_t row0 = m0 + wm + am * 16 + (lane >> 2);
        #pragma unroll
        for (int bn = 0; bn < 8; bn++) {
            size_t col = n0 + wn + bn * 8 + (lane & 3) * 2;
            float2 bv = *(const float2*)(bias + col);
            float2 v0 = {d[am][bn][0] + bv.x, d[am][bn][1] + bv.y};
            float2 v1 = {d[am][bn][2] + bv.x, d[am][bn][3] + bv.y};
            *(float2*)(out + row0 * N_DIM + col) = v0;
            *(float2*)(out + (row0 + 8) * N_DIM + col) = v1;
        }
    }
}

// ============================ launch =======================================
extern "C" void kernel_launch(void* const* d_in, const int* in_sizes, int n_in,
                              void* d_out, int out_size) {
    const float* x    = (const float*)d_in[0];
    const float* kn   = (const float*)d_in[1];
    const float* bias = (const float*)d_in[2];
    float* out = (float*)d_out;

    quant_x_kernel<<<M_DIM * (K_DIM / 128) / 8, 256>>>(x);
    quant_w_kernel<<<K_DIM * (N_DIM / 128) / 8, 256>>>(kn);

    cudaFuncSetAttribute(gemm_kernel, cudaFuncAttributeMaxDynamicSharedMemorySize, GEMM_SMEM);
    gemm_kernel<<<(M_DIM / BM) * (N_DIM / BN), 256, GEMM_SMEM>>>(bias, out);
}

// round 4
// speedup vs baseline: 1.0022x; 1.0022x over previous
#include <cuda_runtime.h>
#include <cuda_fp16.h>
#include <cuda_fp8.h>
#include <cstdint>

#define M_DIM 16384
#define N_DIM 4096
#define K_DIM 4096

#define BM 128
#define BN 128
#define BK 64
#define STAGES 3
#define KITERS (K_DIM / BK)            // 64
#define A_BYTES (BM * BK * 2)          // 16384
#define B_BYTES (BK * BN * 2)          // 16384
#define STAGE_BYTES (A_BYTES + B_BYTES)
#define GEMM_SMEM (STAGES * STAGE_BYTES)  // 98304

// Scratch (device globals: allocation-free rule). 128MB + 32MB.
__device__ __align__(1024) __half g_A[(size_t)M_DIM * K_DIM];  // [M,K] dequant fp16
__device__ __align__(1024) __half g_B[(size_t)K_DIM * N_DIM];  // [K,N] dequant fp16

__device__ __forceinline__ uint32_t smem_u32(const void* p) {
    uint32_t a;
    asm("{ .reg .u64 t; cvta.to.shared.u64 t, %1; cvt.u32.u64 %0, t; }" : "=r"(a) : "l"(p));
    return a;
}

// ============================ quantization =================================
// Exactly reproduce: scale = max(amax/448, 1e-12); q = e4m3_rne(x/scale); deq = q*scale
__device__ __forceinline__ void quant4_nored(const float4 v, float amax, __half* h) {
    float scale = fmaxf(__fdiv_rn(amax, 448.0f), 1e-12f);
    float f[4] = {v.x, v.y, v.z, v.w};
    #pragma unroll
    for (int j = 0; j < 4; j++) {
        __nv_fp8_storage_t q =
            __nv_cvt_float_to_fp8(__fdiv_rn(f[j], scale), __NV_SATFINITE, __NV_E4M3);
        __half_raw hr = __nv_cvt_fp8_to_halfraw(q, __NV_E4M3);
        float dq = __half2float(*reinterpret_cast<__half*>(&hr)) * scale;
        h[j] = __float2half_rn(dq);
    }
}

__device__ __forceinline__ float amax4(const float4 v) {
    return fmaxf(fmaxf(fabsf(v.x), fabsf(v.y)), fmaxf(fabsf(v.z), fabsf(v.w)));
}

// Generic: quantize two 128-blocks per warp with interleaved reductions.
// src layout [R, C] float, blocks of 128 along C. w enumerates block pairs.
__device__ __forceinline__ void quant_pair(const float* __restrict__ src, __half* dst,
                                           int w, int blocks_per_row, int C) {
    int lane = threadIdx.x & 31;
    int row = w / (blocks_per_row >> 1);
    int kb = (w % (blocks_per_row >> 1)) * 2;
    size_t off0 = (size_t)row * C + kb * 128 + lane * 4;
    size_t off1 = off0 + 128;
    float4 v0 = __ldg((const float4*)(src + off0));
    float4 v1 = __ldg((const float4*)(src + off1));
    float a0 = amax4(v0), a1 = amax4(v1);
    #pragma unroll
    for (int o = 16; o; o >>= 1) {
        a0 = fmaxf(a0, __shfl_xor_sync(0xFFFFFFFFu, a0, o));
        a1 = fmaxf(a1, __shfl_xor_sync(0xFFFFFFFFu, a1, o));
    }
    __half h0[4], h1[4];
    quant4_nored(v0, a0, h0);
    quant4_nored(v1, a1, h1);
    *(uint2*)(dst + off0) = *(uint2*)h0;
    *(uint2*)(dst + off1) = *(uint2*)h1;
}

__global__ void __launch_bounds__(256) quant_x_kernel(const float* __restrict__ x) {
    int w = blockIdx.x * 8 + (threadIdx.x >> 5);
    quant_pair(x, g_A, w, K_DIM / 128, K_DIM);
}

__global__ void __launch_bounds__(256) quant_w_kernel(const float* __restrict__ kn) {
    int w = blockIdx.x * 8 + (threadIdx.x >> 5);
    quant_pair(kn, g_B, w, N_DIM / 128, N_DIM);
}

// ============================ GEMM =========================================
// A smem: [128 m][64 k] halves, 128B rows, SW128 swizzle.
// B smem: [64 k][128 n] halves, two 64-n panels of 128B rows, SW128 swizzle.
__device__ __forceinline__ void load_stage(uint32_t stage_base, size_t m0, size_t n0,
                                           int tid, int chunk) {
    const int k0 = chunk * BK;
    uint32_t sA = stage_base;
    uint32_t sB = stage_base + A_BYTES;
    #pragma unroll
    for (int j = 0; j < 4; j++) {
        int i = tid + j * 256;
        int r = i >> 3, c = i & 7;
        uint64_t ga = __cvta_generic_to_global(g_A + (m0 + r) * (size_t)K_DIM + k0 + c * 8);
        uint32_t sa = sA + r * 128 + ((c * 16) ^ ((r & 7) * 16));
        asm volatile("cp.async.cg.shared.global [%0], [%1], 16;" :: "r"(sa), "l"(ga));
    }
    #pragma unroll
    for (int j = 0; j < 4; j++) {
        int i = tid + j * 256;
        int r = i >> 4, c = i & 15;
        uint64_t gb = __cvta_generic_to_global(g_B + (size_t)(k0 + r) * N_DIM + n0 + c * 8);
        uint32_t sbp = sB + (c >> 3) * 8192 + r * 128 + (((c & 7) * 16) ^ ((r & 7) * 16));
        asm volatile("cp.async.cg.shared.global [%0], [%1], 16;" :: "r"(sbp), "l"(gb));
    }
    asm volatile("cp.async.commit_group;" ::: "memory");
}

__device__ __forceinline__ void ld_a_frags(uint32_t sA, int wm, int lane, int ks,
                                           uint32_t a[2][4]) {
    #pragma unroll
    for (int am = 0; am < 2; am++) {
        int row = wm + am * 16 + (lane & 15);
        int cb = ks * 32 + (lane >> 4) * 16;
        uint32_t addr = sA + row * 128 + (cb ^ ((row & 7) * 16));
        asm volatile("ldmatrix.sync.aligned.m8n8.x4.shared.b16 {%0,%1,%2,%3}, [%4];"
                     : "=r"(a[am][0]), "=r"(a[am][1]), "=r"(a[am][2]), "=r"(a[am][3])
                     : "r"(addr));
    }
}

__device__ __forceinline__ void ld_b_frags(uint32_t sB, int wn, int lane, int ks,
                                           uint32_t b[8][2]) {
    #pragma unroll
    for (int q = 0; q < 4; q++) {
        int krow = ks * 16 + (lane & 15);
        int ncol = wn + q * 16 + (lane >> 4) * 8;
        uint32_t addr = sB + (ncol >> 6) * 8192 + krow * 128 +
                        (((ncol & 63) * 2) ^ ((krow & 7) * 16));
        uint32_t r0, r1, r2, r3;
        asm volatile("ldmatrix.sync.aligned.m8n8.x4.trans.shared.b16 {%0,%1,%2,%3}, [%4];"
                     : "=r"(r0), "=r"(r1), "=r"(r2), "=r"(r3) : "r"(addr));
        b[q * 2][0] = r0; b[q * 2][1] = r1;
        b[q * 2 + 1][0] = r2; b[q * 2 + 1][1] = r3;
    }
}

__global__ void __launch_bounds__(256, 2) gemm_kernel(const float* __restrict__ bias,
                                                      float* __restrict__ out) {
    extern __shared__ char smem_raw[];
    uint32_t sb = smem_u32(smem_raw);
    int tid = threadIdx.x, wid = tid >> 5, lane = tid & 31;

    // tile mapping with M-group swizzle for L2 reuse (8 mt x 32 nt per group)
    int bid = blockIdx.x;
    int g = bid >> 8, r = bid & 255;
    int mt = g * 8 + (r & 7);
    int nt = r >> 3;
    size_t m0 = (size_t)mt * BM, n0 = (size_t)nt * BN;
    int wm = (wid & 3) * 32, wn = (wid >> 2) * 64;

    float d[2][8][4];
    #pragma unroll
    for (int i = 0; i < 2; i++)
        #pragma unroll
        for (int j = 0; j < 8; j++)
            #pragma unroll
            for (int q = 0; q < 4; q++) d[i][j][q] = 0.0f;

    load_stage(sb, m0, n0, tid, 0);
    load_stage(sb + STAGE_BYTES, m0, n0, tid, 1);

    uint32_t a[2][2][4], b[2][8][2];

    for (int it = 0; it < KITERS; it++) {
        int s = it % 3;
        if (it + 2 < KITERS) asm volatile("cp.async.wait_group 1;" ::: "memory");
        else                 asm volatile("cp.async.wait_group 0;" ::: "memory");
        __syncthreads();
        if (it + 2 < KITERS)
            load_stage(sb + ((it + 2) % 3) * STAGE_BYTES, m0, n0, tid, it + 2);

        uint32_t sA = sb + s * STAGE_BYTES;
        uint32_t sB = sA + A_BYTES;

        ld_a_frags(sA, wm, lane, 0, a[0]);
        ld_b_frags(sB, wn, lane, 0, b[0]);

        #pragma unroll
        for (int ks = 0; ks < 4; ks++) {
            int cur = ks & 1, nxt = cur ^ 1;
            if (ks < 3) {
                ld_a_frags(sA, wm, lane, ks + 1, a[nxt]);
                ld_b_frags(sB, wn, lane, ks + 1, b[nxt]);
            }
            #pragma unroll
            for (int am = 0; am < 2; am++)
                #pragma unroll
                for (int bn = 0; bn < 8; bn++) {
                    asm volatile(
                        "mma.sync.aligned.m16n8k16.row.col.f32.f16.f16.f32 "
                        "{%0,%1,%2,%3}, {%4,%5,%6,%7}, {%8,%9}, {%0,%1,%2,%3};"
                        : "+f"(d[am][bn][0]), "+f"(d[am][bn][1]),
                          "+f"(d[am][bn][2]), "+f"(d[am][bn][3])
                        : "r"(a[cur][am][0]), "r"(a[cur][am][1]),
                          "r"(a[cur][am][2]), "r"(a[cur][am][3]),
                          "r"(b[cur][bn][0]), "r"(b[cur][bn][1]));
                }
        }
    }

    // Epilogue: direct register -> gmem (streaming stores), add bias.
    #pragma unroll
    for (int am = 0; am < 2; am++) {
        size_t row0 = m0 + wm + am * 16 + (lane >> 2);
        #pragma unroll
        for (int bn = 0; bn < 8; bn++) {
            size_t col = n0 + wn + bn * 8 + (lane & 3) * 2;
            float2 bv = *(const float2*)(bias + col);
            float x0 = d[am][bn][0] + bv.x, y0 = d[am][bn][1] + bv.y;
            float x1 = d[am][bn][2] + bv.x, y1 = d[am][bn][3] + bv.y;
            float* p0 = out + row0 * N_DIM + col;
            float* p1 = out + (row0 + 8) * N_DIM + col;
            asm volatile("st.global.cs.v2.f32 [%0], {%1,%2};" :: "l"(p0), "f"(x0), "f"(y0)
                         : "memory");
            asm volatile("st.global.cs.v2.f32 [%0], {%1,%2};" :: "l"(p1), "f"(x1), "f"(y1)
                         : "memory");
        }
    }
}

// ============================ launch =======================================
extern "C" void kernel_launch(void* const* d_in, const int* in_sizes, int n_in,
                              void* d_out, int out_size) {
    const float* x    = (const float*)d_in[0];
    const float* kn   = (const float*)d_in[1];
    const float* bias = (const float*)d_in[2];
    float* out = (float*)d_out;

    // one warp per 2 blocks of 128
    quant_x_kernel<<<(M_DIM * (K_DIM / 128) / 2) / 8, 256>>>(x);
    quant_w_kernel<<<(K_DIM * (N_DIM / 128) / 2) / 8, 256>>>(kn);

    cudaFuncSetAttribute(gemm_kernel, cudaFuncAttributeMaxDynamicSharedMemorySize, GEMM_SMEM);
    gemm_kernel<<<(M_DIM / BM) * (N_DIM / BN), 256, GEMM_SMEM>>>(bias, out);
}